// round 4
// baseline (speedup 1.0000x reference)
#include <cuda_runtime.h>
#include <cstdint>

#define N_ROWS 131072
#define DIM    32
#define NLAYER 4
#define NE     256
#define BETA   0.25f
#define TPB    64
#define RPT    2
#define NBLK   (N_ROWS / (TPB * RPT))   // 1024
#define PAD    36                        // padded codebook row stride (floats); 144B, 16B-aligned

// Scratch (no allocs allowed): per-block loss partials + completion counter
__device__ double       g_part[NBLK];
__device__ unsigned int g_count = 0;

__device__ __forceinline__ uint64_t pack2(float lo, float hi) {
    uint64_t v;
    asm("mov.b64 %0, {%1, %2};" : "=l"(v) : "f"(lo), "f"(hi));
    return v;
}
// d += a*b (packed f32x2)
__device__ __forceinline__ void fma2(uint64_t& d, uint64_t a, uint64_t b) {
    asm("fma.rn.f32x2 %0, %1, %2, %0;" : "+l"(d) : "l"(a), "l"(b));
}
// return a*b + c (packed f32x2)
__device__ __forceinline__ uint64_t fma2g(uint64_t a, uint64_t b, uint64_t c) {
    uint64_t d;
    asm("fma.rn.f32x2 %0, %1, %2, %3;" : "=l"(d) : "l"(a), "l"(b), "l"(c));
    return d;
}
__device__ __forceinline__ uint64_t add2(uint64_t a, uint64_t b) {
    uint64_t v;
    asm("add.rn.f32x2 %0, %1, %2;" : "=l"(v) : "l"(a), "l"(b));
    return v;
}
__device__ __forceinline__ void unpack2(uint64_t v, float& lo, float& hi) {
    asm("mov.b64 {%0, %1}, %2;" : "=f"(lo), "=f"(hi) : "l"(v));
}

__global__ __launch_bounds__(TPB, 6)
void rvq_main_kernel(const float* __restrict__ x,
                     const float* __restrict__ codebooks,
                     float* __restrict__ out)
{
    // dynamic smem: [NE*PAD] padded codebook + [NE] squared norms  (~37.9 KB)
    extern __shared__ float smem[];
    float* sc  = smem;             // NE * PAD
    float* ccn = smem + NE * PAD;  // NE

    const int tid = threadIdx.x;
    const size_t row0 = (size_t)blockIdx.x * (TPB * RPT) + tid;
    const size_t row1 = row0 + TPB;

    // Residuals in packed f32x2 form: 16 u64 per row
    uint64_t ra[DIM / 2], rb[DIM / 2];
    {
        const ulonglong2* xa = (const ulonglong2*)(x + row0 * DIM);
        const ulonglong2* xb = (const ulonglong2*)(x + row1 * DIM);
        #pragma unroll
        for (int j = 0; j < DIM / 4; j++) {
            ulonglong2 va = xa[j]; ra[2*j] = va.x; ra[2*j+1] = va.y;
            ulonglong2 vb = xb[j]; rb[2*j] = vb.x; rb[2*j+1] = vb.y;
        }
    }

    const uint64_t NEG1 = pack2(-1.0f, -1.0f);
    int      bia[NLAYER], bib[NLAYER];
    uint64_t lacc_a = 0ull, lacc_b = 0ull;   // packed (0,0)

    for (int l = 0; l < NLAYER; l++) {
        __syncthreads();  // protect smem reuse across layers
        // Stage layer-l codebook into padded smem rows (float4 granularity)
        {
            const float4* gcb = (const float4*)(codebooks + (size_t)l * NE * DIM);
            for (int idx = tid; idx < NE * (DIM / 4); idx += TPB) {
                int e = idx >> 3, j = idx & 7;
                *(float4*)(sc + e * PAD + j * 4) = gcb[idx];
            }
        }
        __syncthreads();
        for (int e = tid; e < NE; e += TPB) {
            const float* c = sc + e * PAD;
            float s = 0.f;
            #pragma unroll
            for (int d = 0; d < DIM; d++) s = fmaf(c[d], c[d], s);
            ccn[e] = s;
        }
        __syncthreads();

        // Argmin over 256 codes; dist = ||c||^2 - 2*dot (rr dropped: shift-invariant)
        float bda = 3.4e38f, bdb = 3.4e38f;
        int   bea = 0,       beb = 0;
        #pragma unroll 2
        for (int e = 0; e < NE; e++) {
            const ulonglong2* c2 = (const ulonglong2*)(sc + e * PAD); // broadcast LDS
            float cc = ccn[e];
            uint64_t a0 = 0ull, a1 = 0ull, b0 = 0ull, b1 = 0ull;
            #pragma unroll
            for (int j = 0; j < DIM / 4; j++) {
                ulonglong2 c = c2[j];
                fma2(a0, ra[2*j + 0], c.x);
                fma2(a1, ra[2*j + 1], c.y);
                fma2(b0, rb[2*j + 0], c.x);
                fma2(b1, rb[2*j + 1], c.y);
            }
            float sa0, sa1, sb0, sb1;
            unpack2(add2(a0, a1), sa0, sa1);
            unpack2(add2(b0, b1), sb0, sb1);
            float da = fmaf(-2.f, sa0, fmaf(-2.f, sa1, cc));
            float db = fmaf(-2.f, sb0, fmaf(-2.f, sb1, cc));
            if (da < bda) { bda = da; bea = e; }   // strict < == first-min (jnp.argmin)
            if (db < bdb) { bdb = db; beb = e; }
        }
        bia[l] = bea; bib[l] = beb;

        // Update: t = r - c (packed); loss += t*t; r = t
        {
            const ulonglong2* cba = (const ulonglong2*)(sc + bea * PAD);
            const ulonglong2* cbb = (const ulonglong2*)(sc + beb * PAD);
            #pragma unroll
            for (int j = 0; j < DIM / 4; j++) {
                ulonglong2 ca = cba[j];
                ulonglong2 cb = cbb[j];
                uint64_t t0 = fma2g(ca.x, NEG1, ra[2*j + 0]);
                uint64_t t1 = fma2g(ca.y, NEG1, ra[2*j + 1]);
                uint64_t u0 = fma2g(cb.x, NEG1, rb[2*j + 0]);
                uint64_t u1 = fma2g(cb.y, NEG1, rb[2*j + 1]);
                fma2(lacc_a, t0, t0); fma2(lacc_a, t1, t1);
                fma2(lacc_b, u0, u0); fma2(lacc_b, u1, u1);
                ra[2*j + 0] = t0; ra[2*j + 1] = t1;
                rb[2*j + 0] = u0; rb[2*j + 1] = u1;
            }
        }
    }

    // x_q = x - r_final (reload x; DRAM is ~free at 0.6%)
    {
        const ulonglong2* xa = (const ulonglong2*)(x + row0 * DIM);
        const ulonglong2* xb = (const ulonglong2*)(x + row1 * DIM);
        ulonglong2* oa = (ulonglong2*)(out + row0 * DIM);
        ulonglong2* ob = (ulonglong2*)(out + row1 * DIM);
        #pragma unroll
        for (int j = 0; j < DIM / 4; j++) {
            ulonglong2 va = xa[j], vb = xb[j], o;
            o.x = fma2g(ra[2*j + 0], NEG1, va.x);
            o.y = fma2g(ra[2*j + 1], NEG1, va.y);
            oa[j] = o;
            o.x = fma2g(rb[2*j + 0], NEG1, vb.x);
            o.y = fma2g(rb[2*j + 1], NEG1, vb.y);
            ob[j] = o;
        }
    }
    // Indices as float, [N, L]; region only 4B-aligned -> scalar stores
    {
        float* oia = out + (size_t)N_ROWS * DIM + 1 + row0 * NLAYER;
        float* oib = out + (size_t)N_ROWS * DIM + 1 + row1 * NLAYER;
        #pragma unroll
        for (int l = 0; l < NLAYER; l++) { oia[l] = (float)bia[l]; oib[l] = (float)bib[l]; }
    }

    // ---- loss: block reduce -> per-block partial -> last block finalizes ----
    float la0, la1, lb0, lb1;
    unpack2(lacc_a, la0, la1);
    unpack2(lacc_b, lb0, lb1);
    float loss_sum = (la0 + la1) + (lb0 + lb1);

    __shared__ float warp_part[TPB / 32];
    #pragma unroll
    for (int off = 16; off > 0; off >>= 1)
        loss_sum += __shfl_down_sync(0xFFFFFFFFu, loss_sum, off);
    const int lane = tid & 31, wid = tid >> 5;
    if (lane == 0) warp_part[wid] = loss_sum;
    __syncthreads();

    __shared__ bool is_last;
    if (tid == 0) {
        float s = warp_part[0] + warp_part[1];
        g_part[blockIdx.x] = (double)s;
        __threadfence();
        unsigned t = atomicAdd(&g_count, 1u);
        is_last = (t == (unsigned)(gridDim.x - 1));
    }
    __syncthreads();

    if (is_last) {
        double acc = 0.0;
        for (int i = tid; i < NBLK; i += TPB) acc += g_part[i];
        double* dsm = (double*)smem;  // reuse dynamic smem
        dsm[tid] = acc;
        __syncthreads();
        #pragma unroll
        for (int s = TPB / 2; s > 0; s >>= 1) {
            if (tid < s) dsm[tid] += dsm[tid + s];
            __syncthreads();
        }
        if (tid == 0) {
            double scale = (1.0 + (double)BETA) /
                           ((double)NLAYER * (double)N_ROWS * (double)DIM);
            out[(size_t)N_ROWS * DIM] = (float)(dsm[0] * scale);
            g_count = 0;  // reset for next graph replay
        }
    }
}

extern "C" void kernel_launch(void* const* d_in, const int* in_sizes, int n_in,
                              void* d_out, int out_size)
{
    const float* x   = (const float*)d_in[0];
    const float* cbs = (const float*)d_in[1];
    float* out       = (float*)d_out;
    (void)in_sizes; (void)n_in; (void)out_size;

    const int smem = (NE * PAD + NE) * sizeof(float);  // 37888 B
    rvq_main_kernel<<<NBLK, TPB, smem>>>(x, cbs, out);
}

// round 5
// speedup vs baseline: 1.0981x; 1.0981x over previous
#include <cuda_runtime.h>
#include <cstdint>

#define N_ROWS 131072
#define DIM    32
#define NLAYER 4
#define NE     256
#define BETA   0.25f
#define TPB    128
#define RPT    2
#define NBLK   (N_ROWS / (TPB * RPT))   // 512
#define PAD    32                        // codebook row stride (floats)

// Scratch (no allocs allowed): per-block loss partials + completion counter
__device__ double       g_part[NBLK];
__device__ unsigned int g_count = 0;

__device__ __forceinline__ uint64_t pack2(float lo, float hi) {
    uint64_t v;
    asm("mov.b64 %0, {%1, %2};" : "=l"(v) : "f"(lo), "f"(hi));
    return v;
}
// d += a*b (packed f32x2)
__device__ __forceinline__ void fma2(uint64_t& d, uint64_t a, uint64_t b) {
    asm("fma.rn.f32x2 %0, %1, %2, %0;" : "+l"(d) : "l"(a), "l"(b));
}
// return a*b + c (packed f32x2)
__device__ __forceinline__ uint64_t fma2g(uint64_t a, uint64_t b, uint64_t c) {
    uint64_t d;
    asm("fma.rn.f32x2 %0, %1, %2, %3;" : "=l"(d) : "l"(a), "l"(b), "l"(c));
    return d;
}
__device__ __forceinline__ uint64_t add2(uint64_t a, uint64_t b) {
    uint64_t v;
    asm("add.rn.f32x2 %0, %1, %2;" : "=l"(v) : "l"(a), "l"(b));
    return v;
}
__device__ __forceinline__ void unpack2(uint64_t v, float& lo, float& hi) {
    asm("mov.b64 {%0, %1}, %2;" : "=f"(lo), "=f"(hi) : "l"(v));
}

__global__ __launch_bounds__(TPB, 4)
void rvq_main_kernel(const float* __restrict__ x,
                     const float* __restrict__ codebooks,
                     float* __restrict__ out)
{
    // dynamic smem: [NE*PAD] codebook + [NE] squared norms  (33 KB)
    extern __shared__ float smem[];
    float* sc  = smem;             // NE * PAD
    float* ccn = smem + NE * PAD;  // NE

    const int tid = threadIdx.x;
    const size_t row0 = (size_t)blockIdx.x * (TPB * RPT) + tid;
    const size_t row1 = row0 + TPB;

    // Residuals in packed f32x2 form: 16 u64 per row
    uint64_t ra[DIM / 2], rb[DIM / 2];
    {
        const ulonglong2* xa = (const ulonglong2*)(x + row0 * DIM);
        const ulonglong2* xb = (const ulonglong2*)(x + row1 * DIM);
        #pragma unroll
        for (int j = 0; j < DIM / 4; j++) {
            ulonglong2 va = xa[j]; ra[2*j] = va.x; ra[2*j+1] = va.y;
            ulonglong2 vb = xb[j]; rb[2*j] = vb.x; rb[2*j+1] = vb.y;
        }
    }

    const uint64_t NEG1 = pack2(-1.0f, -1.0f);
    int      bia[NLAYER], bib[NLAYER];
    uint64_t lacc_a = 0ull, lacc_b = 0ull;   // packed (0,0)

    for (int l = 0; l < NLAYER; l++) {
        __syncthreads();  // protect smem reuse across layers
        // Stage layer-l codebook (coalesced float4; PAD==DIM so direct copy)
        {
            const float4* gcb = (const float4*)(codebooks + (size_t)l * NE * DIM);
            float4* sc4 = (float4*)sc;
            #pragma unroll
            for (int i = tid; i < NE * DIM / 4; i += TPB) sc4[i] = gcb[i];
        }
        __syncthreads();
        for (int e = tid; e < NE; e += TPB) {
            const float* c = sc + e * PAD;
            float s = 0.f;
            #pragma unroll
            for (int d = 0; d < DIM; d++) s = fmaf(c[d], c[d], s);
            ccn[e] = s;
        }
        __syncthreads();

        // Argmin over 256 codes; dist = ||c||^2 - 2*dot (rr dropped: shift-invariant)
        float bda = 3.4e38f, bdb = 3.4e38f;
        int   bea = 0,       beb = 0;
        #pragma unroll 2
        for (int e = 0; e < NE; e++) {
            const ulonglong2* c2 = (const ulonglong2*)(sc + e * PAD); // broadcast LDS
            float cc = ccn[e];
            uint64_t a0 = 0ull, a1 = 0ull, b0 = 0ull, b1 = 0ull;
            #pragma unroll
            for (int j = 0; j < DIM / 4; j++) {
                ulonglong2 c = c2[j];
                fma2(a0, ra[2*j + 0], c.x);
                fma2(a1, ra[2*j + 1], c.y);
                fma2(b0, rb[2*j + 0], c.x);
                fma2(b1, rb[2*j + 1], c.y);
            }
            float sa0, sa1, sb0, sb1;
            unpack2(add2(a0, a1), sa0, sa1);
            unpack2(add2(b0, b1), sb0, sb1);
            float da = fmaf(-2.f, sa0, fmaf(-2.f, sa1, cc));
            float db = fmaf(-2.f, sb0, fmaf(-2.f, sb1, cc));
            if (da < bda) { bda = da; bea = e; }   // strict < == first-min (jnp.argmin)
            if (db < bdb) { bdb = db; beb = e; }
        }
        bia[l] = bea; bib[l] = beb;

        // Update: t = r - c (packed); loss += t*t; r = t
        {
            const ulonglong2* cba = (const ulonglong2*)(sc + bea * PAD);
            const ulonglong2* cbb = (const ulonglong2*)(sc + beb * PAD);
            #pragma unroll
            for (int j = 0; j < DIM / 4; j++) {
                ulonglong2 ca = cba[j];
                ulonglong2 cb = cbb[j];
                uint64_t t0 = fma2g(ca.x, NEG1, ra[2*j + 0]);
                uint64_t t1 = fma2g(ca.y, NEG1, ra[2*j + 1]);
                uint64_t u0 = fma2g(cb.x, NEG1, rb[2*j + 0]);
                uint64_t u1 = fma2g(cb.y, NEG1, rb[2*j + 1]);
                fma2(lacc_a, t0, t0); fma2(lacc_a, t1, t1);
                fma2(lacc_b, u0, u0); fma2(lacc_b, u1, u1);
                ra[2*j + 0] = t0; ra[2*j + 1] = t1;
                rb[2*j + 0] = u0; rb[2*j + 1] = u1;
            }
        }
    }

    // x_q = x - r_final (reload x; DRAM is ~free at 0.6%)
    {
        const ulonglong2* xa = (const ulonglong2*)(x + row0 * DIM);
        const ulonglong2* xb = (const ulonglong2*)(x + row1 * DIM);
        ulonglong2* oa = (ulonglong2*)(out + row0 * DIM);
        ulonglong2* ob = (ulonglong2*)(out + row1 * DIM);
        #pragma unroll
        for (int j = 0; j < DIM / 4; j++) {
            ulonglong2 va = xa[j], vb = xb[j], o;
            o.x = fma2g(ra[2*j + 0], NEG1, va.x);
            o.y = fma2g(ra[2*j + 1], NEG1, va.y);
            oa[j] = o;
            o.x = fma2g(rb[2*j + 0], NEG1, vb.x);
            o.y = fma2g(rb[2*j + 1], NEG1, vb.y);
            ob[j] = o;
        }
    }
    // Indices as float, [N, L]; region only 4B-aligned -> scalar stores
    {
        float* oia = out + (size_t)N_ROWS * DIM + 1 + row0 * NLAYER;
        float* oib = out + (size_t)N_ROWS * DIM + 1 + row1 * NLAYER;
        #pragma unroll
        for (int l = 0; l < NLAYER; l++) { oia[l] = (float)bia[l]; oib[l] = (float)bib[l]; }
    }

    // ---- loss: block reduce -> per-block partial -> last block finalizes ----
    float la0, la1, lb0, lb1;
    unpack2(lacc_a, la0, la1);
    unpack2(lacc_b, lb0, lb1);
    float loss_sum = (la0 + la1) + (lb0 + lb1);

    __shared__ float warp_part[TPB / 32];
    #pragma unroll
    for (int off = 16; off > 0; off >>= 1)
        loss_sum += __shfl_down_sync(0xFFFFFFFFu, loss_sum, off);
    const int lane = tid & 31, wid = tid >> 5;
    if (lane == 0) warp_part[wid] = loss_sum;
    __syncthreads();

    __shared__ bool is_last;
    if (tid == 0) {
        float s = warp_part[0] + warp_part[1] + warp_part[2] + warp_part[3];
        g_part[blockIdx.x] = (double)s;
        __threadfence();
        unsigned t = atomicAdd(&g_count, 1u);
        is_last = (t == (unsigned)(gridDim.x - 1));
    }
    __syncthreads();

    if (is_last) {
        double acc = 0.0;
        for (int i = tid; i < NBLK; i += TPB) acc += g_part[i];
        double* dsm = (double*)smem;  // reuse dynamic smem
        dsm[tid] = acc;
        __syncthreads();
        #pragma unroll
        for (int s = TPB / 2; s > 0; s >>= 1) {
            if (tid < s) dsm[tid] += dsm[tid + s];
            __syncthreads();
        }
        if (tid == 0) {
            double scale = (1.0 + (double)BETA) /
                           ((double)NLAYER * (double)N_ROWS * (double)DIM);
            out[(size_t)N_ROWS * DIM] = (float)(dsm[0] * scale);
            g_count = 0;  // reset for next graph replay
        }
    }
}

extern "C" void kernel_launch(void* const* d_in, const int* in_sizes, int n_in,
                              void* d_out, int out_size)
{
    const float* x   = (const float*)d_in[0];
    const float* cbs = (const float*)d_in[1];
    float* out       = (float*)d_out;
    (void)in_sizes; (void)n_in; (void)out_size;

    const int smem = (NE * PAD + NE) * sizeof(float);  // 33 KB
    rvq_main_kernel<<<NBLK, TPB, smem>>>(x, cbs, out);
}